// round 6
// baseline (speedup 1.0000x reference)
#include <cuda_runtime.h>
#include <stdint.h>
#include <math.h>

#define N_NODES 50000
#define N_EDGES 200000

// ---------------- scratch (static __device__; no allocation allowed) ----------------
__device__ __align__(16) float g_h1 [(size_t)N_EDGES * 256];    // enn hidden 1
__device__ __align__(16) float g_big1[(size_t)N_EDGES * 1024];  // enn hidden 2
__device__ __align__(16) float g_big2[(size_t)N_EDGES * 1024];  // z = elu(h2@w3+b3)
__device__ __align__(16) float g_agg [N_NODES * 64];
__device__ __align__(16) float g_xcur[N_NODES * 64];
__device__ __align__(16) float g_xin [N_NODES * 64];
__device__ __align__(16) float g_hbuf[N_NODES * 64];
__device__ __align__(16) float g_gh1 [N_NODES * 256];
__device__ __align__(16) float g_gh2 [N_NODES * 256];

__device__ __forceinline__ float* sbuf(int id) {
    switch (id) {
        case 1: return g_h1;
        case 2: return g_big1;
        case 3: return g_big2;
        case 4: return g_agg;
        case 5: return g_xcur;
        case 6: return g_xin;
        case 7: return g_hbuf;
        case 8: return g_gh1;
        case 9: return g_gh2;
    }
    return nullptr;
}

__device__ __forceinline__ float elu_f(float v) {
    return v > 0.f ? v : expm1f(v);
}

__device__ __forceinline__ uint32_t f2tf32(float f) {
    uint32_t u;
    asm("cvt.rna.tf32.f32 %0, %1;" : "=r"(u) : "f"(f));
    return u;
}

// =============== tensor-core TF32 GEMM via mma.sync (sm_80+ baseline PTX) ===============
// C = elu(A@B + bias).  A: scratch[Aid] [M,K] fp32 row-major; B: [K,N] fp32 row-major.
// CTA tile 128(M) x 128(N), BK=32. 8 warps: 4(M) x 2(N), warp tile 32x64.
// mma.m16n8k8.tf32: per warp 2 Mfrags x 8 Nfrags x 4 ksteps per slab.
// SMEM holds operands in FRAGMENT-MAJOR layout (pre-swizzled at store) so operand
// fetch is one lds.128 (A) / lds.64 (B) per fragment, conflict-free.
// grid: (N/128 [fast], ceil(M/128)) so CTAs sharing an A slab run concurrently (A L2 reuse).
__global__ __launch_bounds__(256, 2)
void tgemm_mma(int M, int N, int K, int Aid,
               const float* __restrict__ B,
               const float* __restrict__ bias, int Cid)
{
    const float* A = sbuf(Aid);
    float*       C = sbuf(Cid);

    // frag-major operand stores
    __shared__ __align__(16) uint32_t sA[4096];  // [kstep4][mwarp4][mfrag2][t32][v4]
    __shared__ __align__(16) uint32_t sB[4096];  // [kstep4][nwarp2][nfrag8][t32][v2]
    __shared__ float sbias[128];

    const int tid   = threadIdx.x;
    const int lane  = tid & 31;
    const int wid   = tid >> 5;
    const int mwarp = wid >> 1;       // 0..3
    const int nwarp = wid & 1;        // 0..1
    const int m0 = blockIdx.y * 128;
    const int n0 = blockIdx.x * 128;

    if (tid < 128) sbias[tid] = bias[n0 + tid];

    float acc[2][8][4];
#pragma unroll
    for (int i = 0; i < 2; i++)
#pragma unroll
        for (int j = 0; j < 8; j++)
#pragma unroll
            for (int v = 0; v < 4; v++) acc[i][j][v] = 0.f;

    for (int kk = 0; kk < K; kk += 32) {
        __syncthreads();
        // ---- A tile [128 x 32] -> frag-major ----
        // A frag reg v (lane = g*4+t): row = g + (v&1)*8, col = t + (v>>1)*4
#pragma unroll
        for (int it = 0; it < 4; ++it) {
            int idx = (it << 8) + tid;
            int ml  = idx >> 3;          // 0..127
            int k4  = idx & 7;           // float4 index along K
            int gm  = m0 + ml;
            float4 f = make_float4(0.f, 0.f, 0.f, 0.f);
            if (gm < M) f = *(const float4*)(A + (size_t)gm * K + kk + (k4 << 2));
            const float fe[4] = { f.x, f.y, f.z, f.w };
            int mwi  = ml >> 5;          // m-warp 0..3
            int mfr  = (ml >> 4) & 1;    // m-frag within warp tile
            int vA_m = (ml >> 3) & 1;    // v bit0 = row+8 within 16-row frag
#pragma unroll
            for (int e = 0; e < 4; ++e) {
                int kl = (k4 << 2) + e;              // 0..31
                int kstep = kl >> 3;                 // 0..3
                int v = vA_m + (((kl >> 2) & 1) << 1);
                int t = ((ml & 7) << 2) + (kl & 3);  // lane
                int off = (((((kstep << 2) + mwi) << 1) + mfr) * 32 + t) * 4 + v;
                sA[off] = f2tf32(fe[e]);
            }
        }
        // ---- B tile [32 x 128] -> frag-major ----
        // B frag reg v (lane = g*4+t): k = t + v*4, n = g
#pragma unroll
        for (int it = 0; it < 4; ++it) {
            int idx = (it << 8) + tid;
            int kl = idx >> 5;           // 0..31
            int n4 = idx & 31;           // float4 index along N
            float4 f = *(const float4*)(B + (size_t)(kk + kl) * N + n0 + (n4 << 2));
            const float fe[4] = { f.x, f.y, f.z, f.w };
            int kstep = kl >> 3;
            int vB = (kl >> 2) & 1;
#pragma unroll
            for (int e = 0; e < 4; ++e) {
                int nl = (n4 << 2) + e;              // 0..127
                int nwi = nl >> 6;                   // n-warp 0..1
                int nfr = (nl >> 3) & 7;             // n-frag 0..7
                int t = ((nl & 7) << 2) + (kl & 3);  // lane
                int off = (((((kstep << 1) + nwi) << 3) + nfr) * 32 + t) * 2 + vB;
                sB[off] = f2tf32(fe[e]);
            }
        }
        __syncthreads();

        // ---- compute 4 ksteps ----
#pragma unroll
        for (int ks = 0; ks < 4; ++ks) {
            uint32_t a[2][4];
#pragma unroll
            for (int mfr = 0; mfr < 2; ++mfr) {
                uint4 t4 = *(const uint4*)&sA[(((((ks << 2) + mwarp) << 1) + mfr) * 32 + lane) * 4];
                a[mfr][0] = t4.x; a[mfr][1] = t4.y; a[mfr][2] = t4.z; a[mfr][3] = t4.w;
            }
            uint32_t b[8][2];
#pragma unroll
            for (int nfr = 0; nfr < 8; ++nfr) {
                uint2 t2 = *(const uint2*)&sB[(((((ks << 1) + nwarp) << 3) + nfr) * 32 + lane) * 2];
                b[nfr][0] = t2.x; b[nfr][1] = t2.y;
            }
#pragma unroll
            for (int mfr = 0; mfr < 2; ++mfr)
#pragma unroll
                for (int nfr = 0; nfr < 8; ++nfr) {
                    asm volatile(
                        "mma.sync.aligned.m16n8k8.row.col.f32.tf32.tf32.f32 "
                        "{%0,%1,%2,%3}, {%4,%5,%6,%7}, {%8,%9}, {%0,%1,%2,%3};"
                        : "+f"(acc[mfr][nfr][0]), "+f"(acc[mfr][nfr][1]),
                          "+f"(acc[mfr][nfr][2]), "+f"(acc[mfr][nfr][3])
                        : "r"(a[mfr][0]), "r"(a[mfr][1]), "r"(a[mfr][2]), "r"(a[mfr][3]),
                          "r"(b[nfr][0]), "r"(b[nfr][1]));
                }
        }
    }

    // ---- epilogue: bias + ELU, direct stores (float2 per row-frag) ----
    const int g  = lane >> 2;
    const int cp = (lane & 3) << 1;
#pragma unroll
    for (int mfr = 0; mfr < 2; ++mfr) {
        int row0 = m0 + (mwarp << 5) + (mfr << 4) + g;
        int row1 = row0 + 8;
#pragma unroll
        for (int nfr = 0; nfr < 8; ++nfr) {
            int ncol = (nwarp << 6) + (nfr << 3) + cp;   // 0..127 within tile
            float b0 = sbias[ncol], b1 = sbias[ncol + 1];
            if (row0 < M) {
                float2 o;
                o.x = elu_f(acc[mfr][nfr][0] + b0);
                o.y = elu_f(acc[mfr][nfr][1] + b1);
                *(float2*)(C + (size_t)row0 * N + n0 + ncol) = o;
            }
            if (row1 < M) {
                float2 o;
                o.x = elu_f(acc[mfr][nfr][2] + b0);
                o.y = elu_f(acc[mfr][nfr][3] + b1);
                *(float2*)(C + (size_t)row1 * N + n0 + ncol) = o;
            }
        }
    }
}

// ---------------- SIMT tiled GEMM (exact fp32) for small layers -----------------
template<int BM, int BN, int BK, int TM, int TN, bool ELU_ACT, bool ADDD, bool STORE4>
__global__ __launch_bounds__(256, 2)
void gemm_k(int M, int N, int K,
            const float* __restrict__ Aext, int Aid,
            const float* __restrict__ B,
            const float* __restrict__ bias,
            int Did, int Cid,
            float* __restrict__ out4, int layer)
{
    const float* A = (Aid == 0) ? Aext : sbuf(Aid);
    const float* D = ADDD ? sbuf(Did) : nullptr;
    float*       C = sbuf(Cid);

    __shared__ float As[BK][BM];
    __shared__ float Bs[BK][BN];

    const int tid = threadIdx.x;
    constexpr int TW = BN / TN;
    const int tx = tid % TW;
    const int ty = tid / TW;
    const int m0 = blockIdx.y * BM;
    const int n0 = blockIdx.x * BN;

    float acc[TM][TN];
#pragma unroll
    for (int i = 0; i < TM; i++)
#pragma unroll
        for (int j = 0; j < TN; j++) acc[i][j] = 0.f;

    constexpr int A_ITERS = (BM * BK) / (256 * 4);
    constexpr int B_ITERS = (BK * BN) / (256 * 4);

    for (int kk = 0; kk < K; kk += BK) {
#pragma unroll
        for (int it = 0; it < A_ITERS; ++it) {
            int i = tid * 4 + it * 1024;
            int r = i / BK;
            int c = i % BK;
            int m = m0 + r;
            float4 v;
            if (m < M) v = *(const float4*)(A + (size_t)m * K + kk + c);
            else       v = make_float4(0.f, 0.f, 0.f, 0.f);
            As[c + 0][r] = v.x;
            As[c + 1][r] = v.y;
            As[c + 2][r] = v.z;
            As[c + 3][r] = v.w;
        }
#pragma unroll
        for (int it = 0; it < B_ITERS; ++it) {
            int i = tid * 4 + it * 1024;
            int r = i / BN;
            int c = i % BN;
            *(float4*)(&Bs[r][c]) = *(const float4*)(B + (size_t)(kk + r) * N + n0 + c);
        }
        __syncthreads();

#pragma unroll
        for (int k = 0; k < BK; k++) {
            float a[TM], b[TN];
#pragma unroll
            for (int i = 0; i < TM; i += 4)
                *(float4*)&a[i] = *(const float4*)&As[k][ty * TM + i];
#pragma unroll
            for (int j = 0; j < TN; j += 4)
                *(float4*)&b[j] = *(const float4*)&Bs[k][tx * TN + j];
#pragma unroll
            for (int i = 0; i < TM; i++)
#pragma unroll
                for (int j = 0; j < TN; j++)
                    acc[i][j] = fmaf(a[i], b[j], acc[i][j]);
        }
        __syncthreads();
    }

#pragma unroll
    for (int i = 0; i < TM; i++) {
        int m = m0 + ty * TM + i;
        if (m >= M) continue;
#pragma unroll
        for (int j = 0; j < TN; j++) {
            int n = n0 + tx * TN + j;
            float v = acc[i][j] + bias[n];
            if (ADDD) v += D[(size_t)m * N + n];
            if (ELU_ACT) v = elu_f(v);
            C[(size_t)m * N + n] = v;
            if (STORE4) out4[(size_t)m * 256 + n * 4 + layer] = v;
        }
    }
}

// ---------------- small helper kernels ----------------
__global__ void zero_agg_k() {
    int i = blockIdx.x * 256 + threadIdx.x;
    if (i < N_NODES * 64) g_agg[i] = 0.f;
}

__global__ void msg_scatter_k(const float* __restrict__ x,
                              const int* __restrict__ ei)
{
    int e = blockIdx.x;
    int o = threadIdx.x;  // 64 threads
    __shared__ float xs[16];
    int s = ei[e];
    int d = ei[N_EDGES + e];
    if (s < 0 || s >= N_NODES || d < 0 || d >= N_NODES) return;
    if (o < 16) xs[o] = x[(size_t)s * 16 + o];
    __syncthreads();
    float acc = 0.f;
    const float* zr = g_big2 + (size_t)e * 1024;
#pragma unroll
    for (int i = 0; i < 16; i++)
        acc = fmaf(xs[i], zr[i * 64 + o], acc);
    atomicAdd(&g_agg[d * 64 + o], acc);
}

__global__ void elu_copy_k() {
    int i = blockIdx.x * 256 + threadIdx.x;
    if (i < N_NODES * 64) {
        float w = elu_f(g_xcur[i]);
        g_xin[i] = w;
        g_hbuf[i] = w;
    }
}

__global__ void gather_scatter_k(const int* __restrict__ ei) {
    int idx = blockIdx.x * 256 + threadIdx.x;
    if (idx >= N_EDGES * 64) return;
    int e = idx >> 6;
    int o = idx & 63;
    int s = ei[e];
    int d = ei[N_EDGES + e];
    if (s < 0 || s >= N_NODES || d < 0 || d >= N_NODES) return;
    atomicAdd(&g_hbuf[d * 64 + o], g_xin[s * 64 + o]);
}

// ---------------- launch ----------------
static inline int cdiv(int a, int b) { return (a + b - 1) / b; }

extern "C" void kernel_launch(void* const* d_in, const int* in_sizes, int n_in,
                              void* d_out, int out_size)
{
    const float* x   = (const float*)d_in[0];
    const int*   ei  = (const int*)d_in[1];
    const float* ea  = (const float*)d_in[2];
    const float* ew1 = (const float*)d_in[3];
    const float* eb1 = (const float*)d_in[4];
    const float* ew2 = (const float*)d_in[5];
    const float* eb2 = (const float*)d_in[6];
    const float* ew3 = (const float*)d_in[7];
    const float* eb3 = (const float*)d_in[8];
    const float* rw  = (const float*)d_in[9];
    const float* rb  = (const float*)d_in[10];
    const float* gw1 = (const float*)d_in[11];
    const float* gb1 = (const float*)d_in[12];
    const float* gw2 = (const float*)d_in[13];
    const float* gb2 = (const float*)d_in[14];
    const float* gw3 = (const float*)d_in[15];
    const float* gb3 = (const float*)d_in[16];
    float* out = (float*)d_out;

    // ---- Layer 0: NNConv ----
    // h1 = elu(edge_attr @ enn_w1 + b1)   [200000,16]@[16,256]  (SIMT, tiny)
    gemm_k<128,128,16,8,8, true,false,false>
        <<<dim3(2, cdiv(N_EDGES,128)), 256>>>(N_EDGES, 256, 16,
            ea, 0, ew1, eb1, 0, 1, nullptr, 0);
    // h2 = elu(h1 @ enn_w2 + b2)          [200000,256]@[256,1024]  (tf32 mma.sync)
    tgemm_mma<<<dim3(1024/128, cdiv(N_EDGES,128)), 256>>>(N_EDGES, 1024, 256, 1, ew2, eb2, 2);
    // z = elu(h2 @ enn_w3 + b3)           [200000,1024]@[1024,1024] (tf32 mma.sync)
    tgemm_mma<<<dim3(1024/128, cdiv(N_EDGES,128)), 256>>>(N_EDGES, 1024, 1024, 2, ew3, eb3, 3);

    // agg = segment_sum(einsum(x[src], w_e), dst)
    zero_agg_k<<<cdiv(N_NODES*64, 256), 256>>>();
    msg_scatter_k<<<N_EDGES, 64>>>(x, ei);

    // xcur = x @ root_w + agg + root_b ; store out[:,:,0]
    gemm_k<128,64,16,8,4, false,true,true>
        <<<dim3(1, cdiv(N_NODES,128)), 256>>>(N_NODES, 64, 16,
            x, 0, rw, rb, 4, 5, out, 0);

    // ---- Layers 1..3: GINConv (exact fp32 SIMT) ----
    for (int l = 0; l < 3; l++) {
        elu_copy_k<<<cdiv(N_NODES*64, 256), 256>>>();
        gather_scatter_k<<<cdiv(N_EDGES*64, 256), 256>>>(ei);
        gemm_k<128,128,16,8,8, true,false,false>
            <<<dim3(2, cdiv(N_NODES,128)), 256>>>(N_NODES, 256, 64,
                nullptr, 7, gw1 + (size_t)l*64*256, gb1 + l*256, 0, 8, nullptr, 0);
        gemm_k<128,128,16,8,8, true,false,false>
            <<<dim3(2, cdiv(N_NODES,128)), 256>>>(N_NODES, 256, 256,
                nullptr, 8, gw2 + (size_t)l*256*256, gb2 + l*256, 0, 9, nullptr, 0);
        gemm_k<128,64,16,8,4, false,false,true>
            <<<dim3(1, cdiv(N_NODES,128)), 256>>>(N_NODES, 64, 256,
                nullptr, 9, gw3 + (size_t)l*256*64, gb3 + l*64, 0, 5, out, l + 1);
    }
}